// round 4
// baseline (speedup 1.0000x reference)
#include <cuda_runtime.h>
#include <math.h>

#define BB 2
#define SS 2048
#define DD 768
#define HH 12
#define DK 64
#define MTOT (BB*SS)   // 4096

// Scratch (allocation-free: device globals)
__device__ float g_Q[BB*SS*DD];
__device__ float g_K[BB*SS*DD];
__device__ float g_V[BB*SS*DD];
__device__ float g_C[BB*SS*DD];

// ---------------------------------------------------------------------------
// GEMM: C[M,N] = A[M,K] @ W[N,K]^T + bias[N]   (torch Linear)
// 64x64 block tile, BK=16, 256 threads, 4x4 per thread.
// ---------------------------------------------------------------------------
__global__ __launch_bounds__(256)
void gemm_nt_bias(const float* __restrict__ A, const float* __restrict__ W,
                  const float* __restrict__ bias, float* __restrict__ C,
                  int M, int N, int K)
{
    __shared__ float As[16][68];   // +4 pad: keeps 16B alignment for LDS.128
    __shared__ float Ws[16][68];

    const int bm = blockIdx.y * 64;
    const int bn = blockIdx.x * 64;
    const int tid = (int)threadIdx.x;

    const int tr = (tid >> 4) << 2;   // 0..60 step 4 (C row offset)
    const int tc = (tid & 15) << 2;   // 0..60 step 4 (C col offset)

    const int lr = tid >> 2;          // 0..63 (load row)
    const int lc = (tid & 3) << 2;    // 0,4,8,12 (load k offset)

    const float* Aptr = A + (size_t)(bm + lr) * K + lc;
    const float* Wptr = W + (size_t)(bn + lr) * K + lc;

    float acc[4][4] = {};

    for (int k0 = 0; k0 < K; k0 += 16) {
        float4 av = *(const float4*)(Aptr + k0);
        float4 wv = *(const float4*)(Wptr + k0);
        As[lc + 0][lr] = av.x; As[lc + 1][lr] = av.y;
        As[lc + 2][lr] = av.z; As[lc + 3][lr] = av.w;
        Ws[lc + 0][lr] = wv.x; Ws[lc + 1][lr] = wv.y;
        Ws[lc + 2][lr] = wv.z; Ws[lc + 3][lr] = wv.w;
        __syncthreads();

        #pragma unroll
        for (int kk = 0; kk < 16; kk++) {
            float a[4], w[4];
            #pragma unroll
            for (int i = 0; i < 4; i++) a[i] = As[kk][tr + i];
            #pragma unroll
            for (int j = 0; j < 4; j++) w[j] = Ws[kk][tc + j];
            #pragma unroll
            for (int i = 0; i < 4; i++)
                #pragma unroll
                for (int j = 0; j < 4; j++)
                    acc[i][j] = fmaf(a[i], w[j], acc[i][j]);
        }
        __syncthreads();
    }

    #pragma unroll
    for (int i = 0; i < 4; i++) {
        float* crow = C + (size_t)(bm + tr + i) * N + bn + tc;
        #pragma unroll
        for (int j = 0; j < 4; j++)
            crow[j] = acc[i][j] + bias[bn + tc + j];
    }
}

// ---------------------------------------------------------------------------
// Flash attention (causal). One thread = one query row.
// Block: 128 threads = 128 q rows for one (b,h). K/V tiles of 32 rows in smem.
// Masked scores get exactly -10000.0f (reference semantics); exp underflows
// to 0 identically to the reference softmax.
// ---------------------------------------------------------------------------
__global__ __launch_bounds__(128)
void attn_kernel()
{
    const int b  = blockIdx.z;
    const int h  = blockIdx.y;
    const int q0 = blockIdx.x * 128;
    const int tid = (int)threadIdx.x;
    const int q  = q0 + tid;

    __shared__ float Ks[32][64];
    __shared__ float Vs[32][64];

    float qreg[64], o[64];
    const float* qp = g_Q + ((size_t)(b * SS + q)) * DD + h * DK;
    #pragma unroll
    for (int d = 0; d < 64; d += 4) {
        float4 v = *(const float4*)(qp + d);
        qreg[d] = v.x; qreg[d+1] = v.y; qreg[d+2] = v.z; qreg[d+3] = v.w;
    }
    #pragma unroll
    for (int d = 0; d < 64; d++) o[d] = 0.f;

    float m = -1e30f, l = 0.f;

    const int nkt = (q0 + 128) / 32;   // causal: only tiles with k <= q0+127

    for (int kt = 0; kt < nkt; kt++) {
        const int k0 = kt * 32;
        __syncthreads();
        // Load 32x64 K and V tiles: 512 float4 each, 128 threads -> 4 each
        #pragma unroll
        for (int i = tid; i < 512; i += 128) {
            const int r = i >> 4;
            const int c = (i & 15) << 2;
            const size_t base = ((size_t)(b * SS + k0 + r)) * DD + h * DK + c;
            *(float4*)&Ks[r][c] = *(const float4*)(g_K + base);
            *(float4*)&Vs[r][c] = *(const float4*)(g_V + base);
        }
        __syncthreads();

        float s[32];
        float tmax = -1e30f;
        #pragma unroll
        for (int j = 0; j < 32; j++) {
            float acc = 0.f;
            #pragma unroll
            for (int d = 0; d < 64; d++)
                acc = fmaf(qreg[d], Ks[j][d], acc);
            acc *= 0.125f;                       // 1/sqrt(64)
            if (k0 + j > q) acc = -10000.0f;     // reference NEG mask
            s[j] = acc;
            tmax = fmaxf(tmax, acc);
        }

        const float mnew  = fmaxf(m, tmax);
        const float alpha = __expf(m - mnew);
        float lsum = 0.f;
        #pragma unroll
        for (int j = 0; j < 32; j++) {
            const float p = __expf(s[j] - mnew);
            s[j] = p;
            lsum += p;
        }
        l = l * alpha + lsum;
        #pragma unroll
        for (int d = 0; d < 64; d++) o[d] *= alpha;
        #pragma unroll
        for (int j = 0; j < 32; j++) {
            const float p = s[j];
            #pragma unroll
            for (int d = 0; d < 64; d++)
                o[d] = fmaf(p, Vs[j][d], o[d]);
        }
        m = mnew;
    }

    const float inv = 1.0f / l;
    float* op = g_C + ((size_t)(b * SS + q)) * DD + h * DK;
    #pragma unroll
    for (int d = 0; d < 64; d += 4) {
        float4 v;
        v.x = o[d] * inv; v.y = o[d+1] * inv;
        v.z = o[d+2] * inv; v.w = o[d+3] * inv;
        *(float4*)(op + d) = v;
    }
}

// ---------------------------------------------------------------------------
// Launch
// inputs: 0=query 1=key 2=value 3=mask 4=Wq 5=bq 6=Wk 7=bk 8=Wv 9=bv 10=Wo 11=bo
// ---------------------------------------------------------------------------
extern "C" void kernel_launch(void* const* d_in, const int* in_sizes, int n_in,
                              void* d_out, int out_size)
{
    (void)in_sizes; (void)n_in; (void)out_size;
    const float* query = (const float*)d_in[0];
    const float* key   = (const float*)d_in[1];
    const float* value = (const float*)d_in[2];
    const float* Wq = (const float*)d_in[4];
    const float* bq = (const float*)d_in[5];
    const float* Wk = (const float*)d_in[6];
    const float* bk = (const float*)d_in[7];
    const float* Wv = (const float*)d_in[8];
    const float* bv = (const float*)d_in[9];
    const float* Wo = (const float*)d_in[10];
    const float* bo = (const float*)d_in[11];
    float* out = (float*)d_out;

    float *pQ, *pK, *pV, *pC;
    cudaGetSymbolAddress((void**)&pQ, g_Q);
    cudaGetSymbolAddress((void**)&pK, g_K);
    cudaGetSymbolAddress((void**)&pV, g_V);
    cudaGetSymbolAddress((void**)&pC, g_C);

    dim3 gGemm(DD / 64, MTOT / 64);     // (12, 64)
    gemm_nt_bias<<<gGemm, 256>>>(query, Wq, bq, pQ, MTOT, DD, DD);
    gemm_nt_bias<<<gGemm, 256>>>(key,   Wk, bk, pK, MTOT, DD, DD);
    gemm_nt_bias<<<gGemm, 256>>>(value, Wv, bv, pV, MTOT, DD, DD);

    dim3 gAttn(SS / 128, HH, BB);        // (16, 12, 2)
    attn_kernel<<<gAttn, 128>>>();

    gemm_nt_bias<<<gGemm, 256>>>(pC, Wo, bo, out, MTOT, DD, DD);
}

// round 6
// speedup vs baseline: 1.2180x; 1.2180x over previous
#include <cuda_runtime.h>
#include <math.h>

#define BB 2
#define SS 2048
#define DD 768
#define HH 12
#define DK 64
#define MTOT (BB*SS)   // 4096

// Scratch (allocation-free: device globals)
__device__ float g_Q[BB*SS*DD];
__device__ float g_K[BB*SS*DD];
__device__ float g_V[BB*SS*DD];
__device__ float g_C[BB*SS*DD];

// ---------------------------------------------------------------------------
// GEMM: C[M,N] = A[M,K] @ W[N,K]^T + bias[N]   (torch Linear)
// 64x64 block tile, BK=16, 256 threads, 4x4 per thread.  (unchanged: ~75% of
// fp32 FMA ceiling already)
// ---------------------------------------------------------------------------
__global__ __launch_bounds__(256)
void gemm_nt_bias(const float* __restrict__ A, const float* __restrict__ W,
                  const float* __restrict__ bias, float* __restrict__ C,
                  int M, int N, int K)
{
    __shared__ float As[16][68];
    __shared__ float Ws[16][68];

    const int bm = blockIdx.y * 64;
    const int bn = blockIdx.x * 64;
    const int tid = (int)threadIdx.x;

    const int tr = (tid >> 4) << 2;
    const int tc = (tid & 15) << 2;

    const int lr = tid >> 2;
    const int lc = (tid & 3) << 2;

    const float* Aptr = A + (size_t)(bm + lr) * K + lc;
    const float* Wptr = W + (size_t)(bn + lr) * K + lc;

    float acc[4][4] = {};

    for (int k0 = 0; k0 < K; k0 += 16) {
        float4 av = *(const float4*)(Aptr + k0);
        float4 wv = *(const float4*)(Wptr + k0);
        As[lc + 0][lr] = av.x; As[lc + 1][lr] = av.y;
        As[lc + 2][lr] = av.z; As[lc + 3][lr] = av.w;
        Ws[lc + 0][lr] = wv.x; Ws[lc + 1][lr] = wv.y;
        Ws[lc + 2][lr] = wv.z; Ws[lc + 3][lr] = wv.w;
        __syncthreads();

        #pragma unroll
        for (int kk = 0; kk < 16; kk++) {
            float a[4], w[4];
            #pragma unroll
            for (int i = 0; i < 4; i++) a[i] = As[kk][tr + i];
            #pragma unroll
            for (int j = 0; j < 4; j++) w[j] = Ws[kk][tc + j];
            #pragma unroll
            for (int i = 0; i < 4; i++)
                #pragma unroll
                for (int j = 0; j < 4; j++)
                    acc[i][j] = fmaf(a[i], w[j], acc[i][j]);
        }
        __syncthreads();
    }

    #pragma unroll
    for (int i = 0; i < 4; i++) {
        float* crow = C + (size_t)(bm + tr + i) * N + bn + tc;
        #pragma unroll
        for (int j = 0; j < 4; j++)
            crow[j] = acc[i][j] + bias[bn + tc + j];
    }
}

// ---------------------------------------------------------------------------
// Flash attention, FA2-style block tiling.
// Block = 64 query rows of one (b,h). 256 threads (16x16 thread grid).
//   S-phase: S(64x32) = Q(64x64) @ K(32x64)^T   -- 4x2 per-thread tile
//   softmax: one thread per row (online m/l state in smem)
//   O-phase: O(64x64) += P(64x32) @ V(32x64)    -- 4x4 per-thread tile
// Q staged transposed (Qt[d][m]) once; K staged transposed (Kt[d][n]) per
// tile; P staged transposed (Ps[n][m], stride 68 -> 16B-aligned rows AND
// conflict-free column reads in softmax).
// ---------------------------------------------------------------------------
__global__ __launch_bounds__(256)
void attn_kernel()
{
    const int b  = blockIdx.z;
    const int h  = blockIdx.y;
    const int qb = (int)gridDim.x - 1 - (int)blockIdx.x;  // longest rows first
    const int q0 = qb * 64;
    const int tid = (int)threadIdx.x;
    const int tr = tid >> 4;        // 0..15
    const int tc = tid & 15;        // 0..15
    const int r4 = tr << 2;         // row offset 0..60
    const int c4 = tc << 2;         // col offset 0..60
    const int c2 = tc << 1;         // score col offset 0..30

    __shared__ float Qt[64][64];    // Qt[d][m]
    __shared__ float Kt[64][34];    // Kt[d][n], n<32 (pad 34: 8B-aligned LDS.64)
    __shared__ float Vs[32][64];    // Vs[n][d]
    __shared__ float Ps[32][68];    // Ps[n][m] (scores, then probs)
    __shared__ float s_m[64], s_l[64], s_alpha[64];

    // ---- stage Q transposed ----
    #pragma unroll
    for (int i = tid; i < 1024; i += 256) {
        const int m = i >> 4;
        const int cc = (i & 15) << 2;
        const float* p = g_Q + ((size_t)(b * SS + q0 + m)) * DD + h * DK + cc;
        float4 v = *(const float4*)p;
        Qt[cc + 0][m] = v.x; Qt[cc + 1][m] = v.y;
        Qt[cc + 2][m] = v.z; Qt[cc + 3][m] = v.w;
    }
    if (tid < 64) { s_m[tid] = -1e30f; s_l[tid] = 0.f; }

    float O[4][4] = {};
    const int nkt = qb * 2 + 2;     // causal: tiles with k0 <= q0+63

    for (int kt = 0; kt < nkt; kt++) {
        const int k0 = kt * 32;

        __syncthreads();            // prev O-phase done with Ps/Vs (or Q staged)

        // ---- stage K (transposed) and V (natural) ----
        #pragma unroll
        for (int i = tid; i < 512; i += 256) {
            const int r  = i >> 4;
            const int cc = (i & 15) << 2;
            const size_t base = ((size_t)(b * SS + k0 + r)) * DD + h * DK + cc;
            float4 kv = *(const float4*)(g_K + base);
            Kt[cc + 0][r] = kv.x; Kt[cc + 1][r] = kv.y;
            Kt[cc + 2][r] = kv.z; Kt[cc + 3][r] = kv.w;
            *(float4*)&Vs[r][cc] = *(const float4*)(g_V + base);
        }
        __syncthreads();

        // ---- S-phase: 4x2 per-thread tile over k=64 ----
        float acc[4][2] = {};
        #pragma unroll
        for (int kk = 0; kk < 64; kk++) {
            float a[4];
            *(float4*)a = *(const float4*)&Qt[kk][r4];
            const float b0 = Kt[kk][c2];
            const float b1 = Kt[kk][c2 + 1];
            #pragma unroll
            for (int i = 0; i < 4; i++) {
                acc[i][0] = fmaf(a[i], b0, acc[i][0]);
                acc[i][1] = fmaf(a[i], b1, acc[i][1]);
            }
        }
        // scale + causal mask + store transposed
        #pragma unroll
        for (int i = 0; i < 4; i++) {
            const int qg = q0 + r4 + i;
            #pragma unroll
            for (int j = 0; j < 2; j++) {
                const int kg = k0 + c2 + j;
                float s = acc[i][j] * 0.125f;           // 1/sqrt(64)
                if (kg > qg) s = -10000.0f;             // reference NEG mask
                Ps[c2 + j][r4 + i] = s;
            }
        }
        __syncthreads();

        // ---- online softmax: thread t handles row t ----
        if (tid < 64) {
            const float mold = s_m[tid];
            float tmax = mold;
            #pragma unroll
            for (int n = 0; n < 32; n++) tmax = fmaxf(tmax, Ps[n][tid]);
            const float alpha = __expf(mold - tmax);
            float lsum = 0.f;
            #pragma unroll
            for (int n = 0; n < 32; n++) {
                const float p = __expf(Ps[n][tid] - tmax);
                Ps[n][tid] = p;
                lsum += p;
            }
            s_l[tid] = s_l[tid] * alpha + lsum;
            s_m[tid] = tmax;
            s_alpha[tid] = alpha;
        }
        __syncthreads();

        // ---- O-phase: rescale + 4x4 per-thread tile over k=32 ----
        float av[4];
        #pragma unroll
        for (int i = 0; i < 4; i++) av[i] = s_alpha[r4 + i];
        #pragma unroll
        for (int i = 0; i < 4; i++)
            #pragma unroll
            for (int j = 0; j < 4; j++)
                O[i][j] *= av[i];

        #pragma unroll
        for (int kk = 0; kk < 32; kk++) {
            float p[4], v[4];
            *(float4*)p = *(const float4*)&Ps[kk][r4];
            *(float4*)v = *(const float4*)&Vs[kk][c4];
            #pragma unroll
            for (int i = 0; i < 4; i++)
                #pragma unroll
                for (int j = 0; j < 4; j++)
                    O[i][j] = fmaf(p[i], v[j], O[i][j]);
        }
    }

    // ---- epilogue: divide by l, write ctx ----
    #pragma unroll
    for (int i = 0; i < 4; i++) {
        const float inv = 1.0f / s_l[r4 + i];
        float4 v;
        v.x = O[i][0] * inv; v.y = O[i][1] * inv;
        v.z = O[i][2] * inv; v.w = O[i][3] * inv;
        *(float4*)(g_C + ((size_t)(b * SS + q0 + r4 + i)) * DD + h * DK + c4) = v;
    }
}

// ---------------------------------------------------------------------------
// Launch
// inputs: 0=query 1=key 2=value 3=mask 4=Wq 5=bq 6=Wk 7=bk 8=Wv 9=bv 10=Wo 11=bo
// ---------------------------------------------------------------------------
extern "C" void kernel_launch(void* const* d_in, const int* in_sizes, int n_in,
                              void* d_out, int out_size)
{
    (void)in_sizes; (void)n_in; (void)out_size;
    const float* query = (const float*)d_in[0];
    const float* key   = (const float*)d_in[1];
    const float* value = (const float*)d_in[2];
    const float* Wq = (const float*)d_in[4];
    const float* bq = (const float*)d_in[5];
    const float* Wk = (const float*)d_in[6];
    const float* bk = (const float*)d_in[7];
    const float* Wv = (const float*)d_in[8];
    const float* bv = (const float*)d_in[9];
    const float* Wo = (const float*)d_in[10];
    const float* bo = (const float*)d_in[11];
    float* out = (float*)d_out;

    float *pQ, *pK, *pV, *pC;
    cudaGetSymbolAddress((void**)&pQ, g_Q);
    cudaGetSymbolAddress((void**)&pK, g_K);
    cudaGetSymbolAddress((void**)&pV, g_V);
    cudaGetSymbolAddress((void**)&pC, g_C);

    dim3 gGemm(DD / 64, MTOT / 64);     // (12, 64)
    gemm_nt_bias<<<gGemm, 256>>>(query, Wq, bq, pQ, MTOT, DD, DD);
    gemm_nt_bias<<<gGemm, 256>>>(key,   Wk, bk, pK, MTOT, DD, DD);
    gemm_nt_bias<<<gGemm, 256>>>(value, Wv, bv, pV, MTOT, DD, DD);

    dim3 gAttn(SS / 64, HH, BB);         // (32, 12, 2)
    attn_kernel<<<gAttn, 256>>>();

    gemm_nt_bias<<<gGemm, 256>>>(pC, Wo, bo, out, MTOT, DD, DD);
}